// round 5
// baseline (speedup 1.0000x reference)
#include <cuda_runtime.h>
#include <cuda_bf16.h>
#include <cstdint>
#include <math.h>

// Problem constants
#define NN 50000
#define EE 600000
#define DD 128
#define LL 3
#define GTILES 782            // ceil(50000/64)
#define NPAD (GTILES * 64)    // 50048
#define SMP 136               // smem row stride (bf16): conflict-free ldmatrix

// ---------------- device scratch (static; no runtime alloc) ----------------
__device__ float g_x [NPAD * DD];
__device__ float g_y [NPAD * DD];
__device__ float g_y2[NPAD * DD];
__device__ float g_h [NPAD * DD];
__device__ float g_statS[9][DD];    // stage = layer*3 + {gemm1, gemm2, zstats}
__device__ float g_statQ[9][DD];
__device__ __nv_bfloat16 g_bthi[LL * 2 * DD * DD];
__device__ __nv_bfloat16 g_btlo[LL * 2 * DD * DD];
__device__ int  g_countArr[NN];
__device__ int  g_startArr[NN];
__device__ int  g_curArr  [NN];
__device__ int2 g_ssw[EE];          // (src, w bits) grouped by dst

// ---------------- warp-mma helpers ----------------
__device__ __forceinline__ uint32_t smem_u32(const void* p) {
    uint32_t a;
    asm("{ .reg .u64 t; cvta.to.shared.u64 t, %1; cvt.u32.u64 %0, t; }" : "=r"(a) : "l"(p));
    return a;
}
__device__ __forceinline__ void ldsm_x4(uint32_t* r, uint32_t addr) {
    asm volatile("ldmatrix.sync.aligned.m8n8.x4.shared.b16 {%0,%1,%2,%3}, [%4];"
                 : "=r"(r[0]), "=r"(r[1]), "=r"(r[2]), "=r"(r[3]) : "r"(addr));
}
__device__ __forceinline__ void mma_bf16(float* d, const uint32_t* a, const uint32_t* b) {
    asm volatile("mma.sync.aligned.m16n8k16.row.col.f32.bf16.bf16.f32 "
                 "{%0,%1,%2,%3}, {%4,%5,%6,%7}, {%8,%9}, {%0,%1,%2,%3};"
                 : "+f"(d[0]), "+f"(d[1]), "+f"(d[2]), "+f"(d[3])
                 : "r"(a[0]), "r"(a[1]), "r"(a[2]), "r"(a[3]),
                   "r"(b[0]), "r"(b[1]));
}

// BN affine from raw stats: a = g*rsqrt(var+eps), c = b - mean*a
__device__ __forceinline__ void affine_from_stats(
    const float* __restrict__ cs, const float* __restrict__ cq,
    const float* __restrict__ g, const float* __restrict__ b,
    float* sA, float* sC, int t)
{
    if (t < DD) {
        const float invN = 1.f / (float)NN;
        float mean = cs[t] * invN;
        float var  = cq[t] * invN - mean * mean;
        float a = g[t] * rsqrtf(var + 1e-5f);
        sA[t] = a;
        sC[t] = b[t] - mean * a;
    }
}

// ---------------- CSR build ----------------
__global__ void zero_kernel(int* cnt, float* statS, float* statQ) {
    int i = blockIdx.x * blockDim.x + threadIdx.x;
    if (i < NN) cnt[i] = 0;
    if (i < 9 * DD) { statS[i] = 0.f; statQ[i] = 0.f; }
}
__global__ void hist_kernel(const int* __restrict__ dst, int* cnt) {
    int e = blockIdx.x * blockDim.x + threadIdx.x;
    if (e < EE) atomicAdd(cnt + __ldg(dst + e), 1);
}
// Single-block full exclusive scan: 512 threads x 98-element chunks.
__global__ void scan_all_kernel(const int* __restrict__ cnt, int* start, int* cur) {
    __shared__ int ssum[512];
    const int t = threadIdx.x;
    const int base = t * 98;
    int s = 0;
    for (int k = 0; k < 98; k++) {
        int i = base + k;
        if (i < NN) s += cnt[i];
    }
    ssum[t] = s; __syncthreads();
    int x = s;
    for (int d = 1; d < 512; d <<= 1) {
        int y = (t >= d) ? ssum[t - d] : 0;
        __syncthreads();
        x += y; ssum[t] = x; __syncthreads();
    }
    int run = x - s;   // exclusive prefix of this chunk
    for (int k = 0; k < 98; k++) {
        int i = base + k;
        if (i < NN) {
            start[i] = run; cur[i] = run;
            run += cnt[i];
        }
    }
}
__global__ void fill_kernel(const int* __restrict__ src, const int* __restrict__ dst,
                            const float* __restrict__ w, int* cur, int2* ssw) {
    int e = blockIdx.x * blockDim.x + threadIdx.x;
    if (e >= EE) return;
    int d = __ldg(dst + e);
    int slot = atomicAdd(cur + d, 1);
    ssw[slot] = make_int2(__ldg(src + e), __float_as_int(__ldg(w + e)));
}

// x[d] = h[d] + sum_e w*h[src]. Warp per node; 2-way unrolled edge loop.
__global__ void __launch_bounds__(256) gather_kernel(
    const float* __restrict__ hprev, const int* __restrict__ start,
    const int* __restrict__ cnt, const int2* __restrict__ ssw,
    float* __restrict__ x)
{
    int d = (blockIdx.x * blockDim.x + threadIdx.x) >> 5;
    int l = threadIdx.x & 31;
    if (d >= NN) return;
    int st  = __ldg(start + d);
    int deg = __ldg(cnt + d);
    float4 acc0 = *(const float4*)(hprev + (size_t)d * DD + l * 4);
    float4 acc1 = make_float4(0.f, 0.f, 0.f, 0.f);
    int j = 0;
    for (; j + 2 <= deg; j += 2) {
        int2 p0 = __ldg(ssw + st + j);
        int2 p1 = __ldg(ssw + st + j + 1);
        float4 h0 = *(const float4*)(hprev + (size_t)p0.x * DD + l * 4);
        float4 h1 = *(const float4*)(hprev + (size_t)p1.x * DD + l * 4);
        float w0 = __int_as_float(p0.y), w1 = __int_as_float(p1.y);
        acc0.x = fmaf(w0, h0.x, acc0.x); acc1.x = fmaf(w1, h1.x, acc1.x);
        acc0.y = fmaf(w0, h0.y, acc0.y); acc1.y = fmaf(w1, h1.y, acc1.y);
        acc0.z = fmaf(w0, h0.z, acc0.z); acc1.z = fmaf(w1, h1.z, acc1.z);
        acc0.w = fmaf(w0, h0.w, acc0.w); acc1.w = fmaf(w1, h1.w, acc1.w);
    }
    if (j < deg) {
        int2 p = __ldg(ssw + st + j);
        float we = __int_as_float(p.y);
        float4 hv = *(const float4*)(hprev + (size_t)p.x * DD + l * 4);
        acc0.x = fmaf(we, hv.x, acc0.x);
        acc0.y = fmaf(we, hv.y, acc0.y);
        acc0.z = fmaf(we, hv.z, acc0.z);
        acc0.w = fmaf(we, hv.w, acc0.w);
    }
    acc0.x += acc1.x; acc0.y += acc1.y; acc0.z += acc1.z; acc0.w += acc1.w;
    *(float4*)(x + (size_t)d * DD + l * 4) = acc0;
}

// All 6 weight matrices -> transposed hi/lo bf16 splits.
__global__ void wprep_all_kernel(const float* __restrict__ W0s, const float* __restrict__ W1s,
                                 __nv_bfloat16* __restrict__ bhi, __nv_bfloat16* __restrict__ blo)
{
    int idx = blockIdx.x * blockDim.x + threadIdx.x;
    if (idx >= 6 * DD * DD) return;
    int m2 = idx >> 14, r = idx & 16383;
    int k = r >> 7, n = r & 127;
    int layer = m2 >> 1, which = m2 & 1;
    const float* W = (which ? W1s : W0s) + layer * DD * DD;
    float v = W[r];
    __nv_bfloat16 h = __float2bfloat16(v);
    __nv_bfloat16 lo = __float2bfloat16(v - __bfloat162float(h));
    bhi[m2 * DD * DD + n * DD + k] = h;
    blo[m2 * DD * DD + n * DD + k] = lo;
}

// C[64-tile,128] = act(A) @ W, mma.sync bf16 hi/lo 3-pass, fused column stats.
// Affine computed at block entry from raw stats (csIn/cqIn + bn g/b).
__global__ void __launch_bounds__(256, 2) gemm_mma_kernel(
    const float* __restrict__ A,
    const __nv_bfloat16* __restrict__ Bhi, const __nv_bfloat16* __restrict__ Blo,
    float* __restrict__ C,
    const float* __restrict__ csIn, const float* __restrict__ cqIn,
    const float* __restrict__ bng, const float* __restrict__ bnb, int useAffine,
    float* __restrict__ statS, float* __restrict__ statQ)
{
    extern __shared__ __align__(16) char dyn[];
    __nv_bfloat16* sAhi = (__nv_bfloat16*)dyn;
    __nv_bfloat16* sAlo = sAhi + 64 * SMP;
    __nv_bfloat16* sBhi = sAlo + 64 * SMP;
    __nv_bfloat16* sBlo = sBhi + 128 * SMP;
    __shared__ float colS[DD], colQ[DD];
    __shared__ float sAf[DD], sCf[DD];

    const int t = threadIdx.x, w = t >> 5, l = t & 31;
    const int mBase = blockIdx.x * 64;

    if (t < DD) { colS[t] = 0.f; colQ[t] = 0.f; }
    if (useAffine) {
        affine_from_stats(csIn, cqIn, bng, bnb, sAf, sCf, t);
        __syncthreads();
    }

    float4 aa, cc;
    if (useAffine) { aa = ((const float4*)sAf)[l]; cc = ((const float4*)sCf)[l]; }
#pragma unroll
    for (int it = 0; it < 8; it++) {
        int row = it * 8 + w;
        float4 v = ((const float4*)(A + (size_t)(mBase + row) * DD))[l];
        if (useAffine) {
            v.x = fmaxf(fmaf(v.x, aa.x, cc.x), 0.f);
            v.y = fmaxf(fmaf(v.y, aa.y, cc.y), 0.f);
            v.z = fmaxf(fmaf(v.z, aa.z, cc.z), 0.f);
            v.w = fmaxf(fmaf(v.w, aa.w, cc.w), 0.f);
        }
        __nv_bfloat162 h01 = __floats2bfloat162_rn(v.x, v.y);
        __nv_bfloat162 h23 = __floats2bfloat162_rn(v.z, v.w);
        __nv_bfloat162 l01 = __floats2bfloat162_rn(v.x - __low2float(h01), v.y - __high2float(h01));
        __nv_bfloat162 l23 = __floats2bfloat162_rn(v.z - __low2float(h23), v.w - __high2float(h23));
        int off = row * SMP + l * 4;
        *(uint2*)(sAhi + off) = make_uint2(*(uint32_t*)&h01, *(uint32_t*)&h23);
        *(uint2*)(sAlo + off) = make_uint2(*(uint32_t*)&l01, *(uint32_t*)&l23);
    }
#pragma unroll
    for (int it = 0; it < 16; it++) {
        int row = it * 8 + w;
        uint2 hv = ((const uint2*)(Bhi + (size_t)row * DD))[l];
        uint2 lv = ((const uint2*)(Blo + (size_t)row * DD))[l];
        int off = row * SMP + l * 4;
        *(uint2*)(sBhi + off) = hv;
        *(uint2*)(sBlo + off) = lv;
    }
    __syncthreads();

    const int wm = (w >> 1) * 16;
    const int wn = (w & 1) * 64;
    float acc[8][4];
#pragma unroll
    for (int i = 0; i < 8; i++)
#pragma unroll
        for (int j = 0; j < 4; j++) acc[i][j] = 0.f;

    const int arow = wm + (l & 15);
    const int acol = (l >> 4) << 3;
    const int browb = wn + ((l >> 4) & 1) * 8 + (l & 7);
    const int bcol  = ((l >> 3) & 1) << 3;

#pragma unroll
    for (int pass = 0; pass < 3; pass++) {
        const __nv_bfloat16* pA = (pass == 2) ? sAlo : sAhi;
        const __nv_bfloat16* pB = (pass == 1) ? sBlo : sBhi;
#pragma unroll
        for (int kc = 0; kc < 8; kc++) {
            const int k0 = kc * 16;
            uint32_t afr[4];
            ldsm_x4(afr, smem_u32(pA + arow * SMP + k0 + acol));
#pragma unroll
            for (int sn2 = 0; sn2 < 4; sn2++) {
                uint32_t bfr[4];
                ldsm_x4(bfr, smem_u32(pB + (browb + sn2 * 16) * SMP + k0 + bcol));
                mma_bf16(acc[sn2 * 2 + 0], afr, bfr + 0);
                mma_bf16(acc[sn2 * 2 + 1], afr, bfr + 2);
            }
        }
    }

    const int g = l >> 2, tq = l & 3;
    const int row0 = mBase + wm + g;
    const float m0 = (row0 < NN) ? 1.f : 0.f;
    const float m1 = (row0 + 8 < NN) ? 1.f : 0.f;
#pragma unroll
    for (int sn = 0; sn < 8; sn++) {
        int col = wn + sn * 8 + tq * 2;
        float* p0 = C + (size_t)row0 * DD + col;
        *(float2*)p0            = make_float2(acc[sn][0], acc[sn][1]);
        *(float2*)(p0 + 8 * DD) = make_float2(acc[sn][2], acc[sn][3]);
        float v0 = m0 * acc[sn][0], v1 = m0 * acc[sn][1];
        float v2 = m1 * acc[sn][2], v3 = m1 * acc[sn][3];
        float cs0 = v0 + v2, cs1 = v1 + v3;
        float cq0 = v0 * v0 + v2 * v2, cq1 = v1 * v1 + v3 * v3;
#pragma unroll
        for (int dlt = 16; dlt >= 4; dlt >>= 1) {
            cs0 += __shfl_down_sync(0xffffffffu, cs0, dlt);
            cs1 += __shfl_down_sync(0xffffffffu, cs1, dlt);
            cq0 += __shfl_down_sync(0xffffffffu, cq0, dlt);
            cq1 += __shfl_down_sync(0xffffffffu, cq1, dlt);
        }
        if (l < 4) {
            int c0 = wn + sn * 8 + l * 2;
            atomicAdd(&colS[c0], cs0);  atomicAdd(&colS[c0 + 1], cs1);
            atomicAdd(&colQ[c0], cq0);  atomicAdd(&colQ[c0 + 1], cq1);
        }
    }
    __syncthreads();
    if (t < DD) {
        atomicAdd(statS + t, colS[t]);
        atomicAdd(statQ + t, colQ[t]);
    }
}

// stats of relu(bn2(y2)); bn2 affine computed at entry from raw stats.
__global__ void __launch_bounds__(256) zstats_kernel(const float* __restrict__ y2,
                                                     const float* __restrict__ cs2,
                                                     const float* __restrict__ cq2,
                                                     const float* __restrict__ bn2g,
                                                     const float* __restrict__ bn2b,
                                                     float* __restrict__ cs,
                                                     float* __restrict__ cq)
{
    __shared__ float shS[8][DD];
    __shared__ float shQ[8][DD];
    __shared__ float sAf[DD], sCf[DD];
    const int t = threadIdx.x;
    const int c4 = (t & 31) * 4;
    const int rg = t >> 5;
    affine_from_stats(cs2, cq2, bn2g, bn2b, sAf, sCf, t);
    __syncthreads();
    float4 a = *(const float4*)(sAf + c4);
    float4 c = *(const float4*)(sCf + c4);
    float4 s = make_float4(0.f, 0.f, 0.f, 0.f), q = make_float4(0.f, 0.f, 0.f, 0.f);
    for (int m = blockIdx.x * 8 + rg; m < NN; m += gridDim.x * 8) {
        float4 v = *(const float4*)(y2 + (size_t)m * DD + c4);
        v.x = fmaxf(fmaf(v.x, a.x, c.x), 0.f);
        v.y = fmaxf(fmaf(v.y, a.y, c.y), 0.f);
        v.z = fmaxf(fmaf(v.z, a.z, c.z), 0.f);
        v.w = fmaxf(fmaf(v.w, a.w, c.w), 0.f);
        s.x += v.x; s.y += v.y; s.z += v.z; s.w += v.w;
        q.x += v.x * v.x; q.y += v.y * v.y; q.z += v.z * v.z; q.w += v.w * v.w;
    }
    *(float4*)&shS[rg][c4] = s;
    *(float4*)&shQ[rg][c4] = q;
    __syncthreads();
    if (t < DD) {
        float ts = 0.f, tqv = 0.f;
#pragma unroll
        for (int i = 0; i < 8; i++) { ts += shS[i][t]; tqv += shQ[i][t]; }
        atomicAdd(cs + t, ts);
        atomicAdd(cq + t, tqv);
    }
}

// out = bn3(relu(bn2(y2))) (+ optional relu). Both affines computed at entry.
__global__ void __launch_bounds__(256) apply_kernel(
    const float* __restrict__ y2,
    const float* __restrict__ cs2, const float* __restrict__ cq2,
    const float* __restrict__ bn2g, const float* __restrict__ bn2b,
    const float* __restrict__ cs3, const float* __restrict__ cq3,
    const float* __restrict__ bn3g, const float* __restrict__ bn3b,
    float* __restrict__ out, int doRelu)
{
    __shared__ float sA2[DD], sC2[DD], sA3[DD], sC3[DD];
    const int t = threadIdx.x;
    affine_from_stats(cs2, cq2, bn2g, bn2b, sA2, sC2, t);
    affine_from_stats(cs3, cq3, bn3g, bn3b, sA3, sC3, t);
    __syncthreads();
    int gid = blockIdx.x * blockDim.x + t;
    if (gid >= NN * (DD / 4)) return;
    int col4 = (gid & (DD / 4 - 1)) << 2;
    float4 v = ((const float4*)y2)[gid];
    float4 A2 = *(const float4*)(sA2 + col4);
    float4 C2 = *(const float4*)(sC2 + col4);
    float4 A3 = *(const float4*)(sA3 + col4);
    float4 C3 = *(const float4*)(sC3 + col4);
    v.x = fmaxf(fmaf(v.x, A2.x, C2.x), 0.f);
    v.y = fmaxf(fmaf(v.y, A2.y, C2.y), 0.f);
    v.z = fmaxf(fmaf(v.z, A2.z, C2.z), 0.f);
    v.w = fmaxf(fmaf(v.w, A2.w, C2.w), 0.f);
    v.x = fmaf(v.x, A3.x, C3.x);
    v.y = fmaf(v.y, A3.y, C3.y);
    v.z = fmaf(v.z, A3.z, C3.z);
    v.w = fmaf(v.w, A3.w, C3.w);
    if (doRelu) {
        v.x = fmaxf(v.x, 0.f); v.y = fmaxf(v.y, 0.f);
        v.z = fmaxf(v.z, 0.f); v.w = fmaxf(v.w, 0.f);
    }
    ((float4*)out)[gid] = v;
}

// ---------------- launch ----------------
extern "C" void kernel_launch(void* const* d_in, const int* in_sizes, int n_in,
                              void* d_out, int out_size)
{
    const float* h_in = (const float*)d_in[0];
    const int*   edges= (const int*)  d_in[1];
    const float* w    = (const float*)d_in[2];
    const float* W0s  = (const float*)d_in[3];
    const float* W1s  = (const float*)d_in[4];
    const float* bn1g = (const float*)d_in[5];
    const float* bn1b = (const float*)d_in[6];
    const float* bn2g = (const float*)d_in[7];
    const float* bn2b = (const float*)d_in[8];
    const float* bn3g = (const float*)d_in[9];
    const float* bn3b = (const float*)d_in[10];
    const int* src = edges;
    const int* dst = edges + EE;

    float *x, *y, *y2, *h, *sS, *sQ;
    __nv_bfloat16 *bthi, *btlo;
    int *cnt, *startA, *cur;
    int2 *ssw;
    cudaGetSymbolAddress((void**)&x,    g_x);
    cudaGetSymbolAddress((void**)&y,    g_y);
    cudaGetSymbolAddress((void**)&y2,   g_y2);
    cudaGetSymbolAddress((void**)&h,    g_h);
    cudaGetSymbolAddress((void**)&sS,   g_statS);
    cudaGetSymbolAddress((void**)&sQ,   g_statQ);
    cudaGetSymbolAddress((void**)&bthi, g_bthi);
    cudaGetSymbolAddress((void**)&btlo, g_btlo);
    cudaGetSymbolAddress((void**)&cnt,  g_countArr);
    cudaGetSymbolAddress((void**)&startA, g_startArr);
    cudaGetSymbolAddress((void**)&cur,  g_curArr);
    cudaGetSymbolAddress((void**)&ssw,  g_ssw);

    const int GEMM_SMEM = (64 + 64 + 128 + 128) * SMP * 2;   // 104448 B
    cudaFuncSetAttribute(gemm_mma_kernel,
                         cudaFuncAttributeMaxDynamicSharedMemorySize, GEMM_SMEM);

    const int EGRID = (EE + 255) / 256;
    const int NGRID = (NN + 255) / 256;
    const int WGRID = (NN * 32 + 255) / 256;   // 6250 (warp per node)

    zero_kernel <<<NGRID, 256>>>(cnt, sS, sQ);
    hist_kernel <<<EGRID, 256>>>(dst, cnt);
    scan_all_kernel<<<1, 512>>>(cnt, startA, cur);
    fill_kernel <<<EGRID, 256>>>(src, dst, w, cur, ssw);
    wprep_all_kernel<<<(6 * DD * DD + 255) / 256, 256>>>(W0s, W1s, bthi, btlo);

    for (int i = 0; i < LL; i++) {
        const float* hsrc = (i == 0) ? h_in : h;
        gather_kernel<<<WGRID, 256>>>(hsrc, startA, cnt, ssw, x);

        const __nv_bfloat16* b0h = bthi + (i * 2 + 0) * DD * DD;
        const __nv_bfloat16* b0l = btlo + (i * 2 + 0) * DD * DD;
        const __nv_bfloat16* b1h = bthi + (i * 2 + 1) * DD * DD;
        const __nv_bfloat16* b1l = btlo + (i * 2 + 1) * DD * DD;
        float *s1 = sS + (i * 3 + 0) * DD, *q1 = sQ + (i * 3 + 0) * DD;
        float *s2 = sS + (i * 3 + 1) * DD, *q2 = sQ + (i * 3 + 1) * DD;
        float *s3 = sS + (i * 3 + 2) * DD, *q3 = sQ + (i * 3 + 2) * DD;

        gemm_mma_kernel<<<GTILES, 256, GEMM_SMEM>>>(
            x, b0h, b0l, y, nullptr, nullptr, nullptr, nullptr, 0, s1, q1);
        gemm_mma_kernel<<<GTILES, 256, GEMM_SMEM>>>(
            y, b1h, b1l, y2, s1, q1, bn1g + i * DD, bn1b + i * DD, 1, s2, q2);
        zstats_kernel<<<250, 256>>>(y2, s2, q2, bn2g + i * DD, bn2b + i * DD, s3, q3);

        int last = (i == LL - 1);
        apply_kernel<<<WGRID, 256>>>(y2, s2, q2, bn2g + i * DD, bn2b + i * DD,
                                     s3, q3, bn3g + i * DD, bn3b + i * DD,
                                     last ? (float*)d_out : h, last ? 0 : 1);
    }
}

// round 6
// speedup vs baseline: 1.1181x; 1.1181x over previous
#include <cuda_runtime.h>
#include <cuda_bf16.h>
#include <cstdint>
#include <math.h>

// Problem constants
#define NN 50000
#define EE 600000
#define DD 128
#define LL 3
#define GTILES 782            // ceil(50000/64)
#define NPAD (GTILES * 64)    // 50048
#define SMP 136               // smem row stride (bf16): conflict-free ldmatrix
#define NBLK 98               // ceil(NN/512) scan blocks

// ---------------- device scratch (static; no runtime alloc) ----------------
__device__ float g_x [NPAD * DD];
__device__ float g_y [NPAD * DD];
__device__ float g_y2[NPAD * DD];
__device__ float g_statS[9][DD];    // stage = layer*3 + {gemm1, gemm2, zstats}
__device__ float g_statQ[9][DD];
__device__ __nv_bfloat16 g_bthi[LL * 2 * DD * DD];
__device__ __nv_bfloat16 g_btlo[LL * 2 * DD * DD];
__device__ int  g_countArr[NN];
__device__ int  g_startArr[NN];
__device__ int  g_curArr  [NN];
__device__ int  g_bsum[NBLK];
__device__ int  g_boff[NBLK];
__device__ int2 g_ssw[EE];          // (src, w bits) grouped by dst

// ---------------- warp-mma helpers ----------------
__device__ __forceinline__ uint32_t smem_u32(const void* p) {
    uint32_t a;
    asm("{ .reg .u64 t; cvta.to.shared.u64 t, %1; cvt.u32.u64 %0, t; }" : "=r"(a) : "l"(p));
    return a;
}
__device__ __forceinline__ void ldsm_x4(uint32_t* r, uint32_t addr) {
    asm volatile("ldmatrix.sync.aligned.m8n8.x4.shared.b16 {%0,%1,%2,%3}, [%4];"
                 : "=r"(r[0]), "=r"(r[1]), "=r"(r[2]), "=r"(r[3]) : "r"(addr));
}
__device__ __forceinline__ void mma_bf16(float* d, const uint32_t* a, const uint32_t* b) {
    asm volatile("mma.sync.aligned.m16n8k16.row.col.f32.bf16.bf16.f32 "
                 "{%0,%1,%2,%3}, {%4,%5,%6,%7}, {%8,%9}, {%0,%1,%2,%3};"
                 : "+f"(d[0]), "+f"(d[1]), "+f"(d[2]), "+f"(d[3])
                 : "r"(a[0]), "r"(a[1]), "r"(a[2]), "r"(a[3]),
                   "r"(b[0]), "r"(b[1]));
}

// BN affine from raw stats: a = g*rsqrt(var+eps), c = b - mean*a
__device__ __forceinline__ void affine_from_stats(
    const float* __restrict__ cs, const float* __restrict__ cq,
    const float* __restrict__ g, const float* __restrict__ b,
    float* sA, float* sC, int t)
{
    if (t < DD) {
        const float invN = 1.f / (float)NN;
        float mean = cs[t] * invN;
        float var  = cq[t] * invN - mean * mean;
        float a = g[t] * rsqrtf(var + 1e-5f);
        sA[t] = a;
        sC[t] = b[t] - mean * a;
    }
}

// ---------------- CSR build ----------------
__global__ void zero_kernel(int* cnt, float* statS, float* statQ) {
    int i = blockIdx.x * blockDim.x + threadIdx.x;
    if (i < NN) cnt[i] = 0;
    if (i < 9 * DD) { statS[i] = 0.f; statQ[i] = 0.f; }
}
__global__ void hist_kernel(const int* __restrict__ dst, int* cnt) {
    int e = blockIdx.x * blockDim.x + threadIdx.x;
    if (e < EE) atomicAdd(cnt + __ldg(dst + e), 1);
}
__global__ void scan1_kernel(const int* __restrict__ cnt, int* start, int* bsum) {
    __shared__ int sm[512];
    int t = threadIdx.x, idx = blockIdx.x * 512 + t;
    int v = (idx < NN) ? cnt[idx] : 0;
    sm[t] = v; __syncthreads();
    int x = v;
    for (int d = 1; d < 512; d <<= 1) {
        int y = (t >= d) ? sm[t - d] : 0;
        __syncthreads();
        x += y; sm[t] = x; __syncthreads();
    }
    if (idx < NN) start[idx] = x - v;
    if (t == 511) bsum[blockIdx.x] = x;
}
__global__ void scan2_kernel(const int* __restrict__ bsum, int* boff) {
    __shared__ int sm[128];
    int t = threadIdx.x;
    int v = (t < NBLK) ? bsum[t] : 0;
    sm[t] = v; __syncthreads();
    int x = v;
    for (int d = 1; d < 128; d <<= 1) {
        int y = (t >= d) ? sm[t - d] : 0;
        __syncthreads();
        x += y; sm[t] = x; __syncthreads();
    }
    if (t < NBLK) boff[t] = x - v;
}
__global__ void scan3_kernel(int* start, const int* __restrict__ boff, int* cur) {
    int i = blockIdx.x * blockDim.x + threadIdx.x;
    if (i >= NN) return;
    int s = start[i] + boff[i >> 9];
    start[i] = s; cur[i] = s;
}
__global__ void fill_kernel(const int* __restrict__ src, const int* __restrict__ dst,
                            const float* __restrict__ w, int* cur, int2* ssw) {
    int e = blockIdx.x * blockDim.x + threadIdx.x;
    if (e >= EE) return;
    int d = __ldg(dst + e);
    int slot = atomicAdd(cur + d, 1);
    ssw[slot] = make_int2(__ldg(src + e), __float_as_int(__ldg(w + e)));
}

// x[d] = F(feat[d]) + sum_e w*F(feat[src]).
// useF=0: F = identity (layer 0, feat = h_in).
// useF=1: F(v) = relu(bn3(relu(bn2(v)))) with affines from prev layer raw stats.
__global__ void __launch_bounds__(256) gather_kernel(
    const float* __restrict__ feat, const int* __restrict__ start,
    const int* __restrict__ cnt, const int2* __restrict__ ssw,
    float* __restrict__ x, int useF,
    const float* __restrict__ cs2, const float* __restrict__ cq2,
    const float* __restrict__ bn2g, const float* __restrict__ bn2b,
    const float* __restrict__ cs3, const float* __restrict__ cq3,
    const float* __restrict__ bn3g, const float* __restrict__ bn3b)
{
    __shared__ float sA2[DD], sC2[DD], sA3[DD], sC3[DD];
    const int t = threadIdx.x;
    if (useF) {
        affine_from_stats(cs2, cq2, bn2g, bn2b, sA2, sC2, t);
        affine_from_stats(cs3, cq3, bn3g, bn3b, sA3, sC3, t);
        __syncthreads();
    }
    int d = (blockIdx.x * blockDim.x + t) >> 5;
    int l = t & 31;
    if (d >= NN) return;

    float4 A2, C2, A3, C3;
    if (useF) {
        A2 = ((const float4*)sA2)[l]; C2 = ((const float4*)sC2)[l];
        A3 = ((const float4*)sA3)[l]; C3 = ((const float4*)sC3)[l];
    }
    auto F = [&](float4 v) -> float4 {
        if (!useF) return v;
        v.x = fmaxf(fmaf(v.x, A2.x, C2.x), 0.f);
        v.y = fmaxf(fmaf(v.y, A2.y, C2.y), 0.f);
        v.z = fmaxf(fmaf(v.z, A2.z, C2.z), 0.f);
        v.w = fmaxf(fmaf(v.w, A2.w, C2.w), 0.f);
        v.x = fmaxf(fmaf(v.x, A3.x, C3.x), 0.f);
        v.y = fmaxf(fmaf(v.y, A3.y, C3.y), 0.f);
        v.z = fmaxf(fmaf(v.z, A3.z, C3.z), 0.f);
        v.w = fmaxf(fmaf(v.w, A3.w, C3.w), 0.f);
        return v;
    };

    int st  = __ldg(start + d);
    int deg = __ldg(cnt + d);
    float4 acc0 = F(*(const float4*)(feat + (size_t)d * DD + l * 4));
    float4 acc1 = make_float4(0.f, 0.f, 0.f, 0.f);
    int j = 0;
    for (; j + 2 <= deg; j += 2) {
        int2 p0 = __ldg(ssw + st + j);
        int2 p1 = __ldg(ssw + st + j + 1);
        float4 h0 = F(*(const float4*)(feat + (size_t)p0.x * DD + l * 4));
        float4 h1 = F(*(const float4*)(feat + (size_t)p1.x * DD + l * 4));
        float w0 = __int_as_float(p0.y), w1 = __int_as_float(p1.y);
        acc0.x = fmaf(w0, h0.x, acc0.x); acc1.x = fmaf(w1, h1.x, acc1.x);
        acc0.y = fmaf(w0, h0.y, acc0.y); acc1.y = fmaf(w1, h1.y, acc1.y);
        acc0.z = fmaf(w0, h0.z, acc0.z); acc1.z = fmaf(w1, h1.z, acc1.z);
        acc0.w = fmaf(w0, h0.w, acc0.w); acc1.w = fmaf(w1, h1.w, acc1.w);
    }
    if (j < deg) {
        int2 p = __ldg(ssw + st + j);
        float we = __int_as_float(p.y);
        float4 hv = F(*(const float4*)(feat + (size_t)p.x * DD + l * 4));
        acc0.x = fmaf(we, hv.x, acc0.x);
        acc0.y = fmaf(we, hv.y, acc0.y);
        acc0.z = fmaf(we, hv.z, acc0.z);
        acc0.w = fmaf(we, hv.w, acc0.w);
    }
    acc0.x += acc1.x; acc0.y += acc1.y; acc0.z += acc1.z; acc0.w += acc1.w;
    *(float4*)(x + (size_t)d * DD + l * 4) = acc0;
}

// All 6 weight matrices -> transposed hi/lo bf16 splits.
__global__ void wprep_all_kernel(const float* __restrict__ W0s, const float* __restrict__ W1s,
                                 __nv_bfloat16* __restrict__ bhi, __nv_bfloat16* __restrict__ blo)
{
    int idx = blockIdx.x * blockDim.x + threadIdx.x;
    if (idx >= 6 * DD * DD) return;
    int m2 = idx >> 14, r = idx & 16383;
    int k = r >> 7, n = r & 127;
    int layer = m2 >> 1, which = m2 & 1;
    const float* W = (which ? W1s : W0s) + layer * DD * DD;
    float v = W[r];
    __nv_bfloat16 h = __float2bfloat16(v);
    __nv_bfloat16 lo = __float2bfloat16(v - __bfloat162float(h));
    bhi[m2 * DD * DD + n * DD + k] = h;
    blo[m2 * DD * DD + n * DD + k] = lo;
}

// C[64-tile,128] = act(A) @ W, mma.sync bf16 hi/lo 3-pass, fused column stats.
// act = relu(bn1(A)) when useAffine (affine from raw stats at block entry).
__global__ void __launch_bounds__(256, 2) gemm_mma_kernel(
    const float* __restrict__ A,
    const __nv_bfloat16* __restrict__ Bhi, const __nv_bfloat16* __restrict__ Blo,
    float* __restrict__ C,
    const float* __restrict__ csIn, const float* __restrict__ cqIn,
    const float* __restrict__ bng, const float* __restrict__ bnb, int useAffine,
    float* __restrict__ statS, float* __restrict__ statQ)
{
    extern __shared__ __align__(16) char dyn[];
    __nv_bfloat16* sAhi = (__nv_bfloat16*)dyn;
    __nv_bfloat16* sAlo = sAhi + 64 * SMP;
    __nv_bfloat16* sBhi = sAlo + 64 * SMP;
    __nv_bfloat16* sBlo = sBhi + 128 * SMP;
    __shared__ float colS[DD], colQ[DD];
    __shared__ float sAf[DD], sCf[DD];

    const int t = threadIdx.x, w = t >> 5, l = t & 31;
    const int mBase = blockIdx.x * 64;

    if (t < DD) { colS[t] = 0.f; colQ[t] = 0.f; }
    if (useAffine) {
        affine_from_stats(csIn, cqIn, bng, bnb, sAf, sCf, t);
        __syncthreads();
    }

    float4 aa, cc;
    if (useAffine) { aa = ((const float4*)sAf)[l]; cc = ((const float4*)sCf)[l]; }
#pragma unroll
    for (int it = 0; it < 8; it++) {
        int row = it * 8 + w;
        float4 v = ((const float4*)(A + (size_t)(mBase + row) * DD))[l];
        if (useAffine) {
            v.x = fmaxf(fmaf(v.x, aa.x, cc.x), 0.f);
            v.y = fmaxf(fmaf(v.y, aa.y, cc.y), 0.f);
            v.z = fmaxf(fmaf(v.z, aa.z, cc.z), 0.f);
            v.w = fmaxf(fmaf(v.w, aa.w, cc.w), 0.f);
        }
        __nv_bfloat162 h01 = __floats2bfloat162_rn(v.x, v.y);
        __nv_bfloat162 h23 = __floats2bfloat162_rn(v.z, v.w);
        __nv_bfloat162 l01 = __floats2bfloat162_rn(v.x - __low2float(h01), v.y - __high2float(h01));
        __nv_bfloat162 l23 = __floats2bfloat162_rn(v.z - __low2float(h23), v.w - __high2float(h23));
        int off = row * SMP + l * 4;
        *(uint2*)(sAhi + off) = make_uint2(*(uint32_t*)&h01, *(uint32_t*)&h23);
        *(uint2*)(sAlo + off) = make_uint2(*(uint32_t*)&l01, *(uint32_t*)&l23);
    }
#pragma unroll
    for (int it = 0; it < 16; it++) {
        int row = it * 8 + w;
        uint2 hv = ((const uint2*)(Bhi + (size_t)row * DD))[l];
        uint2 lv = ((const uint2*)(Blo + (size_t)row * DD))[l];
        int off = row * SMP + l * 4;
        *(uint2*)(sBhi + off) = hv;
        *(uint2*)(sBlo + off) = lv;
    }
    __syncthreads();

    const int wm = (w >> 1) * 16;
    const int wn = (w & 1) * 64;
    float acc[8][4];
#pragma unroll
    for (int i = 0; i < 8; i++)
#pragma unroll
        for (int j = 0; j < 4; j++) acc[i][j] = 0.f;

    const int arow = wm + (l & 15);
    const int acol = (l >> 4) << 3;
    const int browb = wn + ((l >> 4) & 1) * 8 + (l & 7);
    const int bcol  = ((l >> 3) & 1) << 3;

#pragma unroll
    for (int pass = 0; pass < 3; pass++) {
        const __nv_bfloat16* pA = (pass == 2) ? sAlo : sAhi;
        const __nv_bfloat16* pB = (pass == 1) ? sBlo : sBhi;
#pragma unroll
        for (int kc = 0; kc < 8; kc++) {
            const int k0 = kc * 16;
            uint32_t afr[4];
            ldsm_x4(afr, smem_u32(pA + arow * SMP + k0 + acol));
#pragma unroll
            for (int sn2 = 0; sn2 < 4; sn2++) {
                uint32_t bfr[4];
                ldsm_x4(bfr, smem_u32(pB + (browb + sn2 * 16) * SMP + k0 + bcol));
                mma_bf16(acc[sn2 * 2 + 0], afr, bfr + 0);
                mma_bf16(acc[sn2 * 2 + 1], afr, bfr + 2);
            }
        }
    }

    const int g = l >> 2, tq = l & 3;
    const int row0 = mBase + wm + g;
    const float m0 = (row0 < NN) ? 1.f : 0.f;
    const float m1 = (row0 + 8 < NN) ? 1.f : 0.f;
#pragma unroll
    for (int sn = 0; sn < 8; sn++) {
        int col = wn + sn * 8 + tq * 2;
        float* p0 = C + (size_t)row0 * DD + col;
        *(float2*)p0            = make_float2(acc[sn][0], acc[sn][1]);
        *(float2*)(p0 + 8 * DD) = make_float2(acc[sn][2], acc[sn][3]);
        float v0 = m0 * acc[sn][0], v1 = m0 * acc[sn][1];
        float v2 = m1 * acc[sn][2], v3 = m1 * acc[sn][3];
        float cs0 = v0 + v2, cs1 = v1 + v3;
        float cq0 = v0 * v0 + v2 * v2, cq1 = v1 * v1 + v3 * v3;
#pragma unroll
        for (int dlt = 16; dlt >= 4; dlt >>= 1) {
            cs0 += __shfl_down_sync(0xffffffffu, cs0, dlt);
            cs1 += __shfl_down_sync(0xffffffffu, cs1, dlt);
            cq0 += __shfl_down_sync(0xffffffffu, cq0, dlt);
            cq1 += __shfl_down_sync(0xffffffffu, cq1, dlt);
        }
        if (l < 4) {
            int c0 = wn + sn * 8 + l * 2;
            atomicAdd(&colS[c0], cs0);  atomicAdd(&colS[c0 + 1], cs1);
            atomicAdd(&colQ[c0], cq0);  atomicAdd(&colQ[c0 + 1], cq1);
        }
    }
    __syncthreads();
    if (t < DD) {
        atomicAdd(statS + t, colS[t]);
        atomicAdd(statQ + t, colQ[t]);
    }
}

// stats of relu(bn2(y2)); bn2 affine from raw stats at entry.
__global__ void __launch_bounds__(256) zstats_kernel(const float* __restrict__ y2,
                                                     const float* __restrict__ cs2,
                                                     const float* __restrict__ cq2,
                                                     const float* __restrict__ bn2g,
                                                     const float* __restrict__ bn2b,
                                                     float* __restrict__ cs,
                                                     float* __restrict__ cq)
{
    __shared__ float shS[8][DD];
    __shared__ float shQ[8][DD];
    __shared__ float sAf[DD], sCf[DD];
    const int t = threadIdx.x;
    const int c4 = (t & 31) * 4;
    const int rg = t >> 5;
    affine_from_stats(cs2, cq2, bn2g, bn2b, sAf, sCf, t);
    __syncthreads();
    float4 a = *(const float4*)(sAf + c4);
    float4 c = *(const float4*)(sCf + c4);
    float4 s = make_float4(0.f, 0.f, 0.f, 0.f), q = make_float4(0.f, 0.f, 0.f, 0.f);
    for (int m = blockIdx.x * 8 + rg; m < NN; m += gridDim.x * 8) {
        float4 v = *(const float4*)(y2 + (size_t)m * DD + c4);
        v.x = fmaxf(fmaf(v.x, a.x, c.x), 0.f);
        v.y = fmaxf(fmaf(v.y, a.y, c.y), 0.f);
        v.z = fmaxf(fmaf(v.z, a.z, c.z), 0.f);
        v.w = fmaxf(fmaf(v.w, a.w, c.w), 0.f);
        s.x += v.x; s.y += v.y; s.z += v.z; s.w += v.w;
        q.x += v.x * v.x; q.y += v.y * v.y; q.z += v.z * v.z; q.w += v.w * v.w;
    }
    *(float4*)&shS[rg][c4] = s;
    *(float4*)&shQ[rg][c4] = q;
    __syncthreads();
    if (t < DD) {
        float ts = 0.f, tqv = 0.f;
#pragma unroll
        for (int i = 0; i < 8; i++) { ts += shS[i][t]; tqv += shQ[i][t]; }
        atomicAdd(cs + t, ts);
        atomicAdd(cq + t, tqv);
    }
}

// Final output: out = bn3(relu(bn2(y2))), no trailing relu.
__global__ void __launch_bounds__(256) apply_kernel(
    const float* __restrict__ y2,
    const float* __restrict__ cs2, const float* __restrict__ cq2,
    const float* __restrict__ bn2g, const float* __restrict__ bn2b,
    const float* __restrict__ cs3, const float* __restrict__ cq3,
    const float* __restrict__ bn3g, const float* __restrict__ bn3b,
    float* __restrict__ out)
{
    __shared__ float sA2[DD], sC2[DD], sA3[DD], sC3[DD];
    const int t = threadIdx.x;
    affine_from_stats(cs2, cq2, bn2g, bn2b, sA2, sC2, t);
    affine_from_stats(cs3, cq3, bn3g, bn3b, sA3, sC3, t);
    __syncthreads();
    int gid = blockIdx.x * blockDim.x + t;
    if (gid >= NN * (DD / 4)) return;
    int col4 = (gid & (DD / 4 - 1)) << 2;
    float4 v = ((const float4*)y2)[gid];
    float4 A2 = *(const float4*)(sA2 + col4);
    float4 C2 = *(const float4*)(sC2 + col4);
    float4 A3 = *(const float4*)(sA3 + col4);
    float4 C3 = *(const float4*)(sC3 + col4);
    v.x = fmaxf(fmaf(v.x, A2.x, C2.x), 0.f);
    v.y = fmaxf(fmaf(v.y, A2.y, C2.y), 0.f);
    v.z = fmaxf(fmaf(v.z, A2.z, C2.z), 0.f);
    v.w = fmaxf(fmaf(v.w, A2.w, C2.w), 0.f);
    v.x = fmaf(v.x, A3.x, C3.x);
    v.y = fmaf(v.y, A3.y, C3.y);
    v.z = fmaf(v.z, A3.z, C3.z);
    v.w = fmaf(v.w, A3.w, C3.w);
    ((float4*)out)[gid] = v;
}

// ---------------- launch ----------------
extern "C" void kernel_launch(void* const* d_in, const int* in_sizes, int n_in,
                              void* d_out, int out_size)
{
    const float* h_in = (const float*)d_in[0];
    const int*   edges= (const int*)  d_in[1];
    const float* w    = (const float*)d_in[2];
    const float* W0s  = (const float*)d_in[3];
    const float* W1s  = (const float*)d_in[4];
    const float* bn1g = (const float*)d_in[5];
    const float* bn1b = (const float*)d_in[6];
    const float* bn2g = (const float*)d_in[7];
    const float* bn2b = (const float*)d_in[8];
    const float* bn3g = (const float*)d_in[9];
    const float* bn3b = (const float*)d_in[10];
    const int* src = edges;
    const int* dst = edges + EE;

    float *x, *y, *y2, *sS, *sQ;
    __nv_bfloat16 *bthi, *btlo;
    int *cnt, *startA, *cur, *bsum, *boff;
    int2 *ssw;
    cudaGetSymbolAddress((void**)&x,    g_x);
    cudaGetSymbolAddress((void**)&y,    g_y);
    cudaGetSymbolAddress((void**)&y2,   g_y2);
    cudaGetSymbolAddress((void**)&sS,   g_statS);
    cudaGetSymbolAddress((void**)&sQ,   g_statQ);
    cudaGetSymbolAddress((void**)&bthi, g_bthi);
    cudaGetSymbolAddress((void**)&btlo, g_btlo);
    cudaGetSymbolAddress((void**)&cnt,  g_countArr);
    cudaGetSymbolAddress((void**)&startA, g_startArr);
    cudaGetSymbolAddress((void**)&cur,  g_curArr);
    cudaGetSymbolAddress((void**)&bsum, g_bsum);
    cudaGetSymbolAddress((void**)&boff, g_boff);
    cudaGetSymbolAddress((void**)&ssw,  g_ssw);

    const int GEMM_SMEM = (64 + 64 + 128 + 128) * SMP * 2;   // 104448 B
    cudaFuncSetAttribute(gemm_mma_kernel,
                         cudaFuncAttributeMaxDynamicSharedMemorySize, GEMM_SMEM);

    const int EGRID = (EE + 255) / 256;
    const int NGRID = (NN + 255) / 256;
    const int WGRID = (NN * 32 + 255) / 256;   // 6250 (warp per node)

    zero_kernel <<<NGRID, 256>>>(cnt, sS, sQ);
    hist_kernel <<<EGRID, 256>>>(dst, cnt);
    scan1_kernel<<<NBLK, 512>>>(cnt, startA, bsum);
    scan2_kernel<<<1, 128>>>(bsum, boff);
    scan3_kernel<<<NGRID, 256>>>(startA, boff, cur);
    fill_kernel <<<EGRID, 256>>>(src, dst, w, cur, ssw);
    wprep_all_kernel<<<(6 * DD * DD + 255) / 256, 256>>>(W0s, W1s, bthi, btlo);

    for (int i = 0; i < LL; i++) {
        float *s1 = sS + (i * 3 + 0) * DD, *q1 = sQ + (i * 3 + 0) * DD;
        float *s2 = sS + (i * 3 + 1) * DD, *q2 = sQ + (i * 3 + 1) * DD;
        float *s3 = sS + (i * 3 + 2) * DD, *q3 = sQ + (i * 3 + 2) * DD;

        if (i == 0) {
            gather_kernel<<<WGRID, 256>>>(h_in, startA, cnt, ssw, x, 0,
                                          nullptr, nullptr, nullptr, nullptr,
                                          nullptr, nullptr, nullptr, nullptr);
        } else {
            float *ps2 = sS + ((i - 1) * 3 + 1) * DD, *pq2 = sQ + ((i - 1) * 3 + 1) * DD;
            float *ps3 = sS + ((i - 1) * 3 + 2) * DD, *pq3 = sQ + ((i - 1) * 3 + 2) * DD;
            gather_kernel<<<WGRID, 256>>>(y2, startA, cnt, ssw, x, 1,
                                          ps2, pq2, bn2g + (i - 1) * DD, bn2b + (i - 1) * DD,
                                          ps3, pq3, bn3g + (i - 1) * DD, bn3b + (i - 1) * DD);
        }

        const __nv_bfloat16* b0h = bthi + (i * 2 + 0) * DD * DD;
        const __nv_bfloat16* b0l = btlo + (i * 2 + 0) * DD * DD;
        const __nv_bfloat16* b1h = bthi + (i * 2 + 1) * DD * DD;
        const __nv_bfloat16* b1l = btlo + (i * 2 + 1) * DD * DD;

        gemm_mma_kernel<<<GTILES, 256, GEMM_SMEM>>>(
            x, b0h, b0l, y, nullptr, nullptr, nullptr, nullptr, 0, s1, q1);
        gemm_mma_kernel<<<GTILES, 256, GEMM_SMEM>>>(
            y, b1h, b1l, y2, s1, q1, bn1g + i * DD, bn1b + i * DD, 1, s2, q2);
        zstats_kernel<<<250, 256>>>(y2, s2, q2, bn2g + i * DD, bn2b + i * DD, s3, q3);
    }

    apply_kernel<<<WGRID, 256>>>(y2,
                                 sS + (2 * 3 + 1) * DD, sQ + (2 * 3 + 1) * DD,
                                 bn2g + 2 * DD, bn2b + 2 * DD,
                                 sS + (2 * 3 + 2) * DD, sQ + (2 * 3 + 2) * DD,
                                 bn3g + 2 * DD, bn3b + 2 * DD,
                                 (float*)d_out);
}

// round 7
// speedup vs baseline: 1.1502x; 1.0287x over previous
#include <cuda_runtime.h>
#include <cuda_bf16.h>
#include <cstdint>
#include <math.h>

// Problem constants
#define NN 50000
#define EE 600000
#define DD 128
#define LL 3
#define GTILES 782            // ceil(50000/64)
#define NPAD (GTILES * 64)    // 50048
#define SMP 136               // smem row stride (bf16): conflict-free ldmatrix
#define NBLK 98               // ceil(NN/512) scan blocks

// ---------------- device scratch (static; no runtime alloc) ----------------
__device__ float g_x [NPAD * DD];
__device__ float g_y [NPAD * DD];
__device__ float g_y2[NPAD * DD];
__device__ float g_h [NPAD * DD];
__device__ float g_statS[9][DD];    // stage = layer*3 + {gemm1, gemm2, zstats}
__device__ float g_statQ[9][DD];
__device__ __nv_bfloat16 g_bthi[LL * 2 * DD * DD];
__device__ __nv_bfloat16 g_btlo[LL * 2 * DD * DD];
__device__ int  g_countArr[NN];
__device__ int  g_startArr[NN];
__device__ int  g_curArr  [NN];
__device__ int  g_bsum[NBLK];
__device__ int2 g_ssw[EE];          // (src, w bits) grouped by dst

// ---------------- warp-mma helpers ----------------
__device__ __forceinline__ uint32_t smem_u32(const void* p) {
    uint32_t a;
    asm("{ .reg .u64 t; cvta.to.shared.u64 t, %1; cvt.u32.u64 %0, t; }" : "=r"(a) : "l"(p));
    return a;
}
__device__ __forceinline__ void ldsm_x4(uint32_t* r, uint32_t addr) {
    asm volatile("ldmatrix.sync.aligned.m8n8.x4.shared.b16 {%0,%1,%2,%3}, [%4];"
                 : "=r"(r[0]), "=r"(r[1]), "=r"(r[2]), "=r"(r[3]) : "r"(addr));
}
__device__ __forceinline__ void mma_bf16(float* d, const uint32_t* a, const uint32_t* b) {
    asm volatile("mma.sync.aligned.m16n8k16.row.col.f32.bf16.bf16.f32 "
                 "{%0,%1,%2,%3}, {%4,%5,%6,%7}, {%8,%9}, {%0,%1,%2,%3};"
                 : "+f"(d[0]), "+f"(d[1]), "+f"(d[2]), "+f"(d[3])
                 : "r"(a[0]), "r"(a[1]), "r"(a[2]), "r"(a[3]),
                   "r"(b[0]), "r"(b[1]));
}

// BN affine from raw stats: a = g*rsqrt(var+eps), c = b - mean*a
__device__ __forceinline__ void affine_from_stats(
    const float* __restrict__ cs, const float* __restrict__ cq,
    const float* __restrict__ g, const float* __restrict__ b,
    float* sA, float* sC, int t)
{
    if (t < DD) {
        const float invN = 1.f / (float)NN;
        float mean = cs[t] * invN;
        float var  = cq[t] * invN - mean * mean;
        float a = g[t] * rsqrtf(var + 1e-5f);
        sA[t] = a;
        sC[t] = b[t] - mean * a;
    }
}

// ---------------- CSR build ----------------
__global__ void zero_kernel(int* cnt, float* statS, float* statQ) {
    int i = blockIdx.x * blockDim.x + threadIdx.x;
    if (i < NN) cnt[i] = 0;
    if (i < 9 * DD) { statS[i] = 0.f; statQ[i] = 0.f; }
}
__global__ void hist_kernel(const int* __restrict__ dst, int* cnt) {
    int e = blockIdx.x * blockDim.x + threadIdx.x;
    if (e < EE) atomicAdd(cnt + __ldg(dst + e), 1);
}
__global__ void scan1_kernel(const int* __restrict__ cnt, int* start, int* bsum) {
    __shared__ int sm[512];
    int t = threadIdx.x, idx = blockIdx.x * 512 + t;
    int v = (idx < NN) ? cnt[idx] : 0;
    sm[t] = v; __syncthreads();
    int x = v;
    for (int d = 1; d < 512; d <<= 1) {
        int y = (t >= d) ? sm[t - d] : 0;
        __syncthreads();
        x += y; sm[t] = x; __syncthreads();
    }
    if (idx < NN) start[idx] = x - v;
    if (t == 511) bsum[blockIdx.x] = x;
}
// Finalize scan: each 256-thread block lies inside one 512-chunk; warp 0
// computes that chunk's exclusive offset from bsum, then all apply it.
__global__ void scan3_kernel(int* start, const int* __restrict__ bsum, int* cur) {
    __shared__ int sboff;
    const int t = threadIdx.x;
    const int blk = blockIdx.x >> 1;    // owning 512-chunk index
    if (t < 32) {
        int s = 0;
        for (int j = t; j < blk; j += 32) s += __ldg(bsum + j);
#pragma unroll
        for (int d = 16; d; d >>= 1) s += __shfl_down_sync(0xffffffffu, s, d);
        if (t == 0) sboff = s;
    }
    __syncthreads();
    int i = blockIdx.x * 256 + t;
    if (i >= NN) return;
    int s = start[i] + sboff;
    start[i] = s; cur[i] = s;
}
__global__ void fill_kernel(const int* __restrict__ src, const int* __restrict__ dst,
                            const float* __restrict__ w, int* cur, int2* ssw) {
    int e = blockIdx.x * blockDim.x + threadIdx.x;
    if (e >= EE) return;
    int d = __ldg(dst + e);
    int slot = atomicAdd(cur + d, 1);
    ssw[slot] = make_int2(__ldg(src + e), __float_as_int(__ldg(w + e)));
}

// x[d] = h[d] + sum_e w*h[src]. Warp per node; 4-way unrolled edge loop.
__global__ void __launch_bounds__(256) gather_kernel(
    const float* __restrict__ hprev, const int* __restrict__ start,
    const int* __restrict__ cnt, const int2* __restrict__ ssw,
    float* __restrict__ x)
{
    int d = (blockIdx.x * blockDim.x + threadIdx.x) >> 5;
    int l = threadIdx.x & 31;
    if (d >= NN) return;
    int st  = __ldg(start + d);
    int deg = __ldg(cnt + d);
    float4 a0 = *(const float4*)(hprev + (size_t)d * DD + l * 4);
    float4 a1 = make_float4(0.f, 0.f, 0.f, 0.f);
    float4 a2 = make_float4(0.f, 0.f, 0.f, 0.f);
    float4 a3 = make_float4(0.f, 0.f, 0.f, 0.f);
    int j = 0;
    for (; j + 4 <= deg; j += 4) {
        int2 p0 = __ldg(ssw + st + j);
        int2 p1 = __ldg(ssw + st + j + 1);
        int2 p2 = __ldg(ssw + st + j + 2);
        int2 p3 = __ldg(ssw + st + j + 3);
        float4 h0 = *(const float4*)(hprev + (size_t)p0.x * DD + l * 4);
        float4 h1 = *(const float4*)(hprev + (size_t)p1.x * DD + l * 4);
        float4 h2 = *(const float4*)(hprev + (size_t)p2.x * DD + l * 4);
        float4 h3 = *(const float4*)(hprev + (size_t)p3.x * DD + l * 4);
        float w0 = __int_as_float(p0.y), w1 = __int_as_float(p1.y);
        float w2 = __int_as_float(p2.y), w3 = __int_as_float(p3.y);
        a0.x = fmaf(w0, h0.x, a0.x); a1.x = fmaf(w1, h1.x, a1.x);
        a2.x = fmaf(w2, h2.x, a2.x); a3.x = fmaf(w3, h3.x, a3.x);
        a0.y = fmaf(w0, h0.y, a0.y); a1.y = fmaf(w1, h1.y, a1.y);
        a2.y = fmaf(w2, h2.y, a2.y); a3.y = fmaf(w3, h3.y, a3.y);
        a0.z = fmaf(w0, h0.z, a0.z); a1.z = fmaf(w1, h1.z, a1.z);
        a2.z = fmaf(w2, h2.z, a2.z); a3.z = fmaf(w3, h3.z, a3.z);
        a0.w = fmaf(w0, h0.w, a0.w); a1.w = fmaf(w1, h1.w, a1.w);
        a2.w = fmaf(w2, h2.w, a2.w); a3.w = fmaf(w3, h3.w, a3.w);
    }
    for (; j < deg; j++) {
        int2 p = __ldg(ssw + st + j);
        float we = __int_as_float(p.y);
        float4 hv = *(const float4*)(hprev + (size_t)p.x * DD + l * 4);
        a0.x = fmaf(we, hv.x, a0.x);
        a0.y = fmaf(we, hv.y, a0.y);
        a0.z = fmaf(we, hv.z, a0.z);
        a0.w = fmaf(we, hv.w, a0.w);
    }
    a0.x += a1.x + a2.x + a3.x;
    a0.y += a1.y + a2.y + a3.y;
    a0.z += a1.z + a2.z + a3.z;
    a0.w += a1.w + a2.w + a3.w;
    *(float4*)(x + (size_t)d * DD + l * 4) = a0;
}

// All 6 weight matrices -> transposed hi/lo bf16 splits.
__global__ void wprep_all_kernel(const float* __restrict__ W0s, const float* __restrict__ W1s,
                                 __nv_bfloat16* __restrict__ bhi, __nv_bfloat16* __restrict__ blo)
{
    int idx = blockIdx.x * blockDim.x + threadIdx.x;
    if (idx >= 6 * DD * DD) return;
    int m2 = idx >> 14, r = idx & 16383;
    int k = r >> 7, n = r & 127;
    int layer = m2 >> 1, which = m2 & 1;
    const float* W = (which ? W1s : W0s) + layer * DD * DD;
    float v = W[r];
    __nv_bfloat16 h = __float2bfloat16(v);
    __nv_bfloat16 lo = __float2bfloat16(v - __bfloat162float(h));
    bhi[m2 * DD * DD + n * DD + k] = h;
    blo[m2 * DD * DD + n * DD + k] = lo;
}

// C[64-tile,128] = act(A) @ W, mma.sync bf16 hi/lo 3-pass, fused column stats.
// act = relu(bn1(A)) when useAffine (affine from raw stats at block entry).
__global__ void __launch_bounds__(256, 2) gemm_mma_kernel(
    const float* __restrict__ A,
    const __nv_bfloat16* __restrict__ Bhi, const __nv_bfloat16* __restrict__ Blo,
    float* __restrict__ C,
    const float* __restrict__ csIn, const float* __restrict__ cqIn,
    const float* __restrict__ bng, const float* __restrict__ bnb, int useAffine,
    float* __restrict__ statS, float* __restrict__ statQ)
{
    extern __shared__ __align__(16) char dyn[];
    __nv_bfloat16* sAhi = (__nv_bfloat16*)dyn;
    __nv_bfloat16* sAlo = sAhi + 64 * SMP;
    __nv_bfloat16* sBhi = sAlo + 64 * SMP;
    __nv_bfloat16* sBlo = sBhi + 128 * SMP;
    __shared__ float colS[DD], colQ[DD];
    __shared__ float sAf[DD], sCf[DD];

    const int t = threadIdx.x, w = t >> 5, l = t & 31;
    const int mBase = blockIdx.x * 64;

    if (t < DD) { colS[t] = 0.f; colQ[t] = 0.f; }
    if (useAffine) {
        affine_from_stats(csIn, cqIn, bng, bnb, sAf, sCf, t);
        __syncthreads();
    }

    float4 aa, cc;
    if (useAffine) { aa = ((const float4*)sAf)[l]; cc = ((const float4*)sCf)[l]; }
#pragma unroll
    for (int it = 0; it < 8; it++) {
        int row = it * 8 + w;
        float4 v = ((const float4*)(A + (size_t)(mBase + row) * DD))[l];
        if (useAffine) {
            v.x = fmaxf(fmaf(v.x, aa.x, cc.x), 0.f);
            v.y = fmaxf(fmaf(v.y, aa.y, cc.y), 0.f);
            v.z = fmaxf(fmaf(v.z, aa.z, cc.z), 0.f);
            v.w = fmaxf(fmaf(v.w, aa.w, cc.w), 0.f);
        }
        __nv_bfloat162 h01 = __floats2bfloat162_rn(v.x, v.y);
        __nv_bfloat162 h23 = __floats2bfloat162_rn(v.z, v.w);
        __nv_bfloat162 l01 = __floats2bfloat162_rn(v.x - __low2float(h01), v.y - __high2float(h01));
        __nv_bfloat162 l23 = __floats2bfloat162_rn(v.z - __low2float(h23), v.w - __high2float(h23));
        int off = row * SMP + l * 4;
        *(uint2*)(sAhi + off) = make_uint2(*(uint32_t*)&h01, *(uint32_t*)&h23);
        *(uint2*)(sAlo + off) = make_uint2(*(uint32_t*)&l01, *(uint32_t*)&l23);
    }
#pragma unroll
    for (int it = 0; it < 16; it++) {
        int row = it * 8 + w;
        uint2 hv = ((const uint2*)(Bhi + (size_t)row * DD))[l];
        uint2 lv = ((const uint2*)(Blo + (size_t)row * DD))[l];
        int off = row * SMP + l * 4;
        *(uint2*)(sBhi + off) = hv;
        *(uint2*)(sBlo + off) = lv;
    }
    __syncthreads();

    const int wm = (w >> 1) * 16;
    const int wn = (w & 1) * 64;
    float acc[8][4];
#pragma unroll
    for (int i = 0; i < 8; i++)
#pragma unroll
        for (int j = 0; j < 4; j++) acc[i][j] = 0.f;

    const int arow = wm + (l & 15);
    const int acol = (l >> 4) << 3;
    const int browb = wn + ((l >> 4) & 1) * 8 + (l & 7);
    const int bcol  = ((l >> 3) & 1) << 3;

#pragma unroll
    for (int pass = 0; pass < 3; pass++) {
        const __nv_bfloat16* pA = (pass == 2) ? sAlo : sAhi;
        const __nv_bfloat16* pB = (pass == 1) ? sBlo : sBhi;
#pragma unroll
        for (int kc = 0; kc < 8; kc++) {
            const int k0 = kc * 16;
            uint32_t afr[4];
            ldsm_x4(afr, smem_u32(pA + arow * SMP + k0 + acol));
#pragma unroll
            for (int sn2 = 0; sn2 < 4; sn2++) {
                uint32_t bfr[4];
                ldsm_x4(bfr, smem_u32(pB + (browb + sn2 * 16) * SMP + k0 + bcol));
                mma_bf16(acc[sn2 * 2 + 0], afr, bfr + 0);
                mma_bf16(acc[sn2 * 2 + 1], afr, bfr + 2);
            }
        }
    }

    const int g = l >> 2, tq = l & 3;
    const int row0 = mBase + wm + g;
    const float m0 = (row0 < NN) ? 1.f : 0.f;
    const float m1 = (row0 + 8 < NN) ? 1.f : 0.f;
#pragma unroll
    for (int sn = 0; sn < 8; sn++) {
        int col = wn + sn * 8 + tq * 2;
        float* p0 = C + (size_t)row0 * DD + col;
        *(float2*)p0            = make_float2(acc[sn][0], acc[sn][1]);
        *(float2*)(p0 + 8 * DD) = make_float2(acc[sn][2], acc[sn][3]);
        float v0 = m0 * acc[sn][0], v1 = m0 * acc[sn][1];
        float v2 = m1 * acc[sn][2], v3 = m1 * acc[sn][3];
        float cs0 = v0 + v2, cs1 = v1 + v3;
        float cq0 = v0 * v0 + v2 * v2, cq1 = v1 * v1 + v3 * v3;
#pragma unroll
        for (int dlt = 16; dlt >= 4; dlt >>= 1) {
            cs0 += __shfl_down_sync(0xffffffffu, cs0, dlt);
            cs1 += __shfl_down_sync(0xffffffffu, cs1, dlt);
            cq0 += __shfl_down_sync(0xffffffffu, cq0, dlt);
            cq1 += __shfl_down_sync(0xffffffffu, cq1, dlt);
        }
        if (l < 4) {
            int c0 = wn + sn * 8 + l * 2;
            atomicAdd(&colS[c0], cs0);  atomicAdd(&colS[c0 + 1], cs1);
            atomicAdd(&colQ[c0], cq0);  atomicAdd(&colQ[c0 + 1], cq1);
        }
    }
    __syncthreads();
    if (t < DD) {
        atomicAdd(statS + t, colS[t]);
        atomicAdd(statQ + t, colQ[t]);
    }
}

// stats of relu(bn2(y2)); bn2 affine from raw stats at entry.
__global__ void __launch_bounds__(256) zstats_kernel(const float* __restrict__ y2,
                                                     const float* __restrict__ cs2,
                                                     const float* __restrict__ cq2,
                                                     const float* __restrict__ bn2g,
                                                     const float* __restrict__ bn2b,
                                                     float* __restrict__ cs,
                                                     float* __restrict__ cq)
{
    __shared__ float shS[8][DD];
    __shared__ float shQ[8][DD];
    __shared__ float sAf[DD], sCf[DD];
    const int t = threadIdx.x;
    const int c4 = (t & 31) * 4;
    const int rg = t >> 5;
    affine_from_stats(cs2, cq2, bn2g, bn2b, sAf, sCf, t);
    __syncthreads();
    float4 a = *(const float4*)(sAf + c4);
    float4 c = *(const float4*)(sCf + c4);
    float4 s = make_float4(0.f, 0.f, 0.f, 0.f), q = make_float4(0.f, 0.f, 0.f, 0.f);
    for (int m = blockIdx.x * 8 + rg; m < NN; m += gridDim.x * 8) {
        float4 v = *(const float4*)(y2 + (size_t)m * DD + c4);
        v.x = fmaxf(fmaf(v.x, a.x, c.x), 0.f);
        v.y = fmaxf(fmaf(v.y, a.y, c.y), 0.f);
        v.z = fmaxf(fmaf(v.z, a.z, c.z), 0.f);
        v.w = fmaxf(fmaf(v.w, a.w, c.w), 0.f);
        s.x += v.x; s.y += v.y; s.z += v.z; s.w += v.w;
        q.x += v.x * v.x; q.y += v.y * v.y; q.z += v.z * v.z; q.w += v.w * v.w;
    }
    *(float4*)&shS[rg][c4] = s;
    *(float4*)&shQ[rg][c4] = q;
    __syncthreads();
    if (t < DD) {
        float ts = 0.f, tqv = 0.f;
#pragma unroll
        for (int i = 0; i < 8; i++) { ts += shS[i][t]; tqv += shQ[i][t]; }
        atomicAdd(cs + t, ts);
        atomicAdd(cq + t, tqv);
    }
}

// out = bn3(relu(bn2(y2))) (+ optional relu). Affines from raw stats at entry.
__global__ void __launch_bounds__(256) apply_kernel(
    const float* __restrict__ y2,
    const float* __restrict__ cs2, const float* __restrict__ cq2,
    const float* __restrict__ bn2g, const float* __restrict__ bn2b,
    const float* __restrict__ cs3, const float* __restrict__ cq3,
    const float* __restrict__ bn3g, const float* __restrict__ bn3b,
    float* __restrict__ out, int doRelu)
{
    __shared__ float sA2[DD], sC2[DD], sA3[DD], sC3[DD];
    const int t = threadIdx.x;
    affine_from_stats(cs2, cq2, bn2g, bn2b, sA2, sC2, t);
    affine_from_stats(cs3, cq3, bn3g, bn3b, sA3, sC3, t);
    __syncthreads();
    int gid = blockIdx.x * blockDim.x + t;
    if (gid >= NN * (DD / 4)) return;
    int col4 = (gid & (DD / 4 - 1)) << 2;
    float4 v = ((const float4*)y2)[gid];
    float4 A2 = *(const float4*)(sA2 + col4);
    float4 C2 = *(const float4*)(sC2 + col4);
    float4 A3 = *(const float4*)(sA3 + col4);
    float4 C3 = *(const float4*)(sC3 + col4);
    v.x = fmaxf(fmaf(v.x, A2.x, C2.x), 0.f);
    v.y = fmaxf(fmaf(v.y, A2.y, C2.y), 0.f);
    v.z = fmaxf(fmaf(v.z, A2.z, C2.z), 0.f);
    v.w = fmaxf(fmaf(v.w, A2.w, C2.w), 0.f);
    v.x = fmaf(v.x, A3.x, C3.x);
    v.y = fmaf(v.y, A3.y, C3.y);
    v.z = fmaf(v.z, A3.z, C3.z);
    v.w = fmaf(v.w, A3.w, C3.w);
    if (doRelu) {
        v.x = fmaxf(v.x, 0.f); v.y = fmaxf(v.y, 0.f);
        v.z = fmaxf(v.z, 0.f); v.w = fmaxf(v.w, 0.f);
    }
    ((float4*)out)[gid] = v;
}

// ---------------- launch ----------------
extern "C" void kernel_launch(void* const* d_in, const int* in_sizes, int n_in,
                              void* d_out, int out_size)
{
    const float* h_in = (const float*)d_in[0];
    const int*   edges= (const int*)  d_in[1];
    const float* w    = (const float*)d_in[2];
    const float* W0s  = (const float*)d_in[3];
    const float* W1s  = (const float*)d_in[4];
    const float* bn1g = (const float*)d_in[5];
    const float* bn1b = (const float*)d_in[6];
    const float* bn2g = (const float*)d_in[7];
    const float* bn2b = (const float*)d_in[8];
    const float* bn3g = (const float*)d_in[9];
    const float* bn3b = (const float*)d_in[10];
    const int* src = edges;
    const int* dst = edges + EE;

    float *x, *y, *y2, *h, *sS, *sQ;
    __nv_bfloat16 *bthi, *btlo;
    int *cnt, *startA, *cur, *bsum;
    int2 *ssw;
    cudaGetSymbolAddress((void**)&x,    g_x);
    cudaGetSymbolAddress((void**)&y,    g_y);
    cudaGetSymbolAddress((void**)&y2,   g_y2);
    cudaGetSymbolAddress((void**)&h,    g_h);
    cudaGetSymbolAddress((void**)&sS,   g_statS);
    cudaGetSymbolAddress((void**)&sQ,   g_statQ);
    cudaGetSymbolAddress((void**)&bthi, g_bthi);
    cudaGetSymbolAddress((void**)&btlo, g_btlo);
    cudaGetSymbolAddress((void**)&cnt,  g_countArr);
    cudaGetSymbolAddress((void**)&startA, g_startArr);
    cudaGetSymbolAddress((void**)&cur,  g_curArr);
    cudaGetSymbolAddress((void**)&bsum, g_bsum);
    cudaGetSymbolAddress((void**)&ssw,  g_ssw);

    const int GEMM_SMEM = (64 + 64 + 128 + 128) * SMP * 2;   // 104448 B
    cudaFuncSetAttribute(gemm_mma_kernel,
                         cudaFuncAttributeMaxDynamicSharedMemorySize, GEMM_SMEM);

    const int EGRID = (EE + 255) / 256;
    const int NGRID = (NN + 255) / 256;
    const int WGRID = (NN * 32 + 255) / 256;   // 6250 (warp per node)

    zero_kernel <<<NGRID, 256>>>(cnt, sS, sQ);
    hist_kernel <<<EGRID, 256>>>(dst, cnt);
    scan1_kernel<<<NBLK, 512>>>(cnt, startA, bsum);
    scan3_kernel<<<NGRID, 256>>>(startA, bsum, cur);
    fill_kernel <<<EGRID, 256>>>(src, dst, w, cur, ssw);
    wprep_all_kernel<<<(6 * DD * DD + 255) / 256, 256>>>(W0s, W1s, bthi, btlo);

    for (int i = 0; i < LL; i++) {
        float *s1 = sS + (i * 3 + 0) * DD, *q1 = sQ + (i * 3 + 0) * DD;
        float *s2 = sS + (i * 3 + 1) * DD, *q2 = sQ + (i * 3 + 1) * DD;
        float *s3 = sS + (i * 3 + 2) * DD, *q3 = sQ + (i * 3 + 2) * DD;

        const float* hsrc = (i == 0) ? h_in : h;
        gather_kernel<<<WGRID, 256>>>(hsrc, startA, cnt, ssw, x);

        const __nv_bfloat16* b0h = bthi + (i * 2 + 0) * DD * DD;
        const __nv_bfloat16* b0l = btlo + (i * 2 + 0) * DD * DD;
        const __nv_bfloat16* b1h = bthi + (i * 2 + 1) * DD * DD;
        const __nv_bfloat16* b1l = btlo + (i * 2 + 1) * DD * DD;

        gemm_mma_kernel<<<GTILES, 256, GEMM_SMEM>>>(
            x, b0h, b0l, y, nullptr, nullptr, nullptr, nullptr, 0, s1, q1);
        gemm_mma_kernel<<<GTILES, 256, GEMM_SMEM>>>(
            y, b1h, b1l, y2, s1, q1, bn1g + i * DD, bn1b + i * DD, 1, s2, q2);
        zstats_kernel<<<250, 256>>>(y2, s2, q2, bn2g + i * DD, bn2b + i * DD, s3, q3);

        int last = (i == LL - 1);
        apply_kernel<<<WGRID, 256>>>(y2, s2, q2, bn2g + i * DD, bn2b + i * DD,
                                     s3, q3, bn3g + i * DD, bn3b + i * DD,
                                     last ? (float*)d_out : h, last ? 0 : 1);
    }
}

// round 10
// speedup vs baseline: 1.1791x; 1.0251x over previous
#include <cuda_runtime.h>
#include <cuda_bf16.h>
#include <cstdint>
#include <math.h>

// Problem constants
#define NN 50000
#define EE 600000
#define DD 128
#define LL 3
#define GTILES 782            // ceil(50000/64)
#define NPAD (GTILES * 64)    // 50048
#define SMP 136               // smem row stride (bf16): conflict-free ldmatrix
#define NBLK 98               // ceil(NN/512) scan blocks

// ---------------- device scratch (static; no runtime alloc) ----------------
// Two big buffers only -> working set fits in L2 (see aliasing plan in launch).
__device__ float g_B1[NPAD * DD];   // x  / y2
__device__ float g_B2[NPAD * DD];   // y  / h
__device__ float g_statS[9][DD];    // stage = layer*3 + {gemm1, gemm2, zstats}
__device__ float g_statQ[9][DD];
__device__ __nv_bfloat16 g_bthi[LL * 2 * DD * DD];
__device__ __nv_bfloat16 g_btlo[LL * 2 * DD * DD];
__device__ int  g_countArr[NN];
__device__ int  g_startArr[NN];
__device__ int  g_curArr  [NN];
__device__ int  g_bsum[NBLK];
__device__ int2 g_ssw[EE];          // (src, w bits) grouped by dst

// ---------------- warp-mma helpers ----------------
__device__ __forceinline__ uint32_t smem_u32(const void* p) {
    uint32_t a;
    asm("{ .reg .u64 t; cvta.to.shared.u64 t, %1; cvt.u32.u64 %0, t; }" : "=r"(a) : "l"(p));
    return a;
}
__device__ __forceinline__ void ldsm_x4(uint32_t* r, uint32_t addr) {
    asm volatile("ldmatrix.sync.aligned.m8n8.x4.shared.b16 {%0,%1,%2,%3}, [%4];"
                 : "=r"(r[0]), "=r"(r[1]), "=r"(r[2]), "=r"(r[3]) : "r"(addr));
}
__device__ __forceinline__ void mma_bf16(float* d, const uint32_t* a, const uint32_t* b) {
    asm volatile("mma.sync.aligned.m16n8k16.row.col.f32.bf16.bf16.f32 "
                 "{%0,%1,%2,%3}, {%4,%5,%6,%7}, {%8,%9}, {%0,%1,%2,%3};"
                 : "+f"(d[0]), "+f"(d[1]), "+f"(d[2]), "+f"(d[3])
                 : "r"(a[0]), "r"(a[1]), "r"(a[2]), "r"(a[3]),
                   "r"(b[0]), "r"(b[1]));
}

// BN affine from raw stats: a = g*rsqrt(var+eps), c = b - mean*a
__device__ __forceinline__ void affine_from_stats(
    const float* __restrict__ cs, const float* __restrict__ cq,
    const float* __restrict__ g, const float* __restrict__ b,
    float* sA, float* sC, int t)
{
    if (t < DD) {
        const float invN = 1.f / (float)NN;
        float mean = cs[t] * invN;
        float var  = cq[t] * invN - mean * mean;
        float a = g[t] * rsqrtf(var + 1e-5f);
        sA[t] = a;
        sC[t] = b[t] - mean * a;
    }
}

// ---------------- CSR build ----------------
__global__ void zero_kernel(int* cnt, float* statS, float* statQ) {
    int i = blockIdx.x * blockDim.x + threadIdx.x;
    if (i < NN) cnt[i] = 0;
    if (i < 9 * DD) { statS[i] = 0.f; statQ[i] = 0.f; }
}
__global__ void hist_kernel(const int* __restrict__ dst, int* cnt) {
    int e = blockIdx.x * blockDim.x + threadIdx.x;
    if (e < EE) atomicAdd(cnt + __ldg(dst + e), 1);
}
__global__ void scan1_kernel(const int* __restrict__ cnt, int* start, int* bsum) {
    __shared__ int sm[512];
    int t = threadIdx.x, idx = blockIdx.x * 512 + t;
    int v = (idx < NN) ? cnt[idx] : 0;
    sm[t] = v; __syncthreads();
    int x = v;
    for (int d = 1; d < 512; d <<= 1) {
        int y = (t >= d) ? sm[t - d] : 0;
        __syncthreads();
        x += y; sm[t] = x; __syncthreads();
    }
    if (idx < NN) start[idx] = x - v;
    if (t == 511) bsum[blockIdx.x] = x;
}
// Finalize scan: each 256-thread block lies inside one 512-chunk; warp 0
// computes that chunk's exclusive offset from bsum, then all apply it.
__global__ void scan3_kernel(int* start, const int* __restrict__ bsum, int* cur) {
    __shared__ int sboff;
    const int t = threadIdx.x;
    const int blk = blockIdx.x >> 1;    // owning 512-chunk index
    if (t < 32) {
        int s = 0;
        for (int j = t; j < blk; j += 32) s += __ldg(bsum + j);
#pragma unroll
        for (int d = 16; d; d >>= 1) s += __shfl_down_sync(0xffffffffu, s, d);
        if (t == 0) sboff = s;
    }
    __syncthreads();
    int i = blockIdx.x * 256 + t;
    if (i >= NN) return;
    int s = start[i] + sboff;
    start[i] = s; cur[i] = s;
}
__global__ void fill_kernel(const int* __restrict__ src, const int* __restrict__ dst,
                            const float* __restrict__ w, int* cur, int2* ssw) {
    int e = blockIdx.x * blockDim.x + threadIdx.x;
    if (e >= EE) return;
    int d = __ldg(dst + e);
    int slot = atomicAdd(cur + d, 1);
    ssw[slot] = make_int2(__ldg(src + e), __float_as_int(__ldg(w + e)));
}

// x[d] = h[d] + sum_e w*h[src]. Warp per node; 2-way unrolled edge loop.
__global__ void __launch_bounds__(256) gather_kernel(
    const float* __restrict__ hprev, const int* __restrict__ start,
    const int* __restrict__ cnt, const int2* __restrict__ ssw,
    float* __restrict__ x)
{
    int d = (blockIdx.x * blockDim.x + threadIdx.x) >> 5;
    int l = threadIdx.x & 31;
    if (d >= NN) return;
    int st  = __ldg(start + d);
    int deg = __ldg(cnt + d);
    float4 acc0 = *(const float4*)(hprev + (size_t)d * DD + l * 4);
    float4 acc1 = make_float4(0.f, 0.f, 0.f, 0.f);
    int j = 0;
    for (; j + 2 <= deg; j += 2) {
        int2 p0 = __ldg(ssw + st + j);
        int2 p1 = __ldg(ssw + st + j + 1);
        float4 h0 = *(const float4*)(hprev + (size_t)p0.x * DD + l * 4);
        float4 h1 = *(const float4*)(hprev + (size_t)p1.x * DD + l * 4);
        float w0 = __int_as_float(p0.y), w1 = __int_as_float(p1.y);
        acc0.x = fmaf(w0, h0.x, acc0.x); acc1.x = fmaf(w1, h1.x, acc1.x);
        acc0.y = fmaf(w0, h0.y, acc0.y); acc1.y = fmaf(w1, h1.y, acc1.y);
        acc0.z = fmaf(w0, h0.z, acc0.z); acc1.z = fmaf(w1, h1.z, acc1.z);
        acc0.w = fmaf(w0, h0.w, acc0.w); acc1.w = fmaf(w1, h1.w, acc1.w);
    }
    if (j < deg) {
        int2 p = __ldg(ssw + st + j);
        float we = __int_as_float(p.y);
        float4 hv = *(const float4*)(hprev + (size_t)p.x * DD + l * 4);
        acc0.x = fmaf(we, hv.x, acc0.x);
        acc0.y = fmaf(we, hv.y, acc0.y);
        acc0.z = fmaf(we, hv.z, acc0.z);
        acc0.w = fmaf(we, hv.w, acc0.w);
    }
    acc0.x += acc1.x; acc0.y += acc1.y; acc0.z += acc1.z; acc0.w += acc1.w;
    *(float4*)(x + (size_t)d * DD + l * 4) = acc0;
}

// All 6 weight matrices -> transposed hi/lo bf16 splits.
__global__ void wprep_all_kernel(const float* __restrict__ W0s, const float* __restrict__ W1s,
                                 __nv_bfloat16* __restrict__ bhi, __nv_bfloat16* __restrict__ blo)
{
    int idx = blockIdx.x * blockDim.x + threadIdx.x;
    if (idx >= 6 * DD * DD) return;
    int m2 = idx >> 14, r = idx & 16383;
    int k = r >> 7, n = r & 127;
    int layer = m2 >> 1, which = m2 & 1;
    const float* W = (which ? W1s : W0s) + layer * DD * DD;
    float v = W[r];
    __nv_bfloat16 h = __float2bfloat16(v);
    __nv_bfloat16 lo = __float2bfloat16(v - __bfloat162float(h));
    bhi[m2 * DD * DD + n * DD + k] = h;
    blo[m2 * DD * DD + n * DD + k] = lo;
}

// C[64-tile,128] = act(A) @ W, mma.sync bf16 hi/lo 3-pass, fused column stats.
// act = relu(bn1(A)) when useAffine (affine from raw stats at block entry).
__global__ void __launch_bounds__(256, 2) gemm_mma_kernel(
    const float* __restrict__ A,
    const __nv_bfloat16* __restrict__ Bhi, const __nv_bfloat16* __restrict__ Blo,
    float* __restrict__ C,
    const float* __restrict__ csIn, const float* __restrict__ cqIn,
    const float* __restrict__ bng, const float* __restrict__ bnb, int useAffine,
    float* __restrict__ statS, float* __restrict__ statQ)
{
    extern __shared__ __align__(16) char dyn[];
    __nv_bfloat16* sAhi = (__nv_bfloat16*)dyn;
    __nv_bfloat16* sAlo = sAhi + 64 * SMP;
    __nv_bfloat16* sBhi = sAlo + 64 * SMP;
    __nv_bfloat16* sBlo = sBhi + 128 * SMP;
    __shared__ float colS[DD], colQ[DD];
    __shared__ float sAf[DD], sCf[DD];

    const int t = threadIdx.x, w = t >> 5, l = t & 31;
    const int mBase = blockIdx.x * 64;

    if (t < DD) { colS[t] = 0.f; colQ[t] = 0.f; }
    if (useAffine) {
        affine_from_stats(csIn, cqIn, bng, bnb, sAf, sCf, t);
        __syncthreads();
    }

    float4 aa, cc;
    if (useAffine) { aa = ((const float4*)sAf)[l]; cc = ((const float4*)sCf)[l]; }
#pragma unroll
    for (int it = 0; it < 8; it++) {
        int row = it * 8 + w;
        float4 v = ((const float4*)(A + (size_t)(mBase + row) * DD))[l];
        if (useAffine) {
            v.x = fmaxf(fmaf(v.x, aa.x, cc.x), 0.f);
            v.y = fmaxf(fmaf(v.y, aa.y, cc.y), 0.f);
            v.z = fmaxf(fmaf(v.z, aa.z, cc.z), 0.f);
            v.w = fmaxf(fmaf(v.w, aa.w, cc.w), 0.f);
        }
        __nv_bfloat162 h01 = __floats2bfloat162_rn(v.x, v.y);
        __nv_bfloat162 h23 = __floats2bfloat162_rn(v.z, v.w);
        __nv_bfloat162 l01 = __floats2bfloat162_rn(v.x - __low2float(h01), v.y - __high2float(h01));
        __nv_bfloat162 l23 = __floats2bfloat162_rn(v.z - __low2float(h23), v.w - __high2float(h23));
        int off = row * SMP + l * 4;
        *(uint2*)(sAhi + off) = make_uint2(*(uint32_t*)&h01, *(uint32_t*)&h23);
        *(uint2*)(sAlo + off) = make_uint2(*(uint32_t*)&l01, *(uint32_t*)&l23);
    }
#pragma unroll
    for (int it = 0; it < 16; it++) {
        int row = it * 8 + w;
        uint2 hv = ((const uint2*)(Bhi + (size_t)row * DD))[l];
        uint2 lv = ((const uint2*)(Blo + (size_t)row * DD))[l];
        int off = row * SMP + l * 4;
        *(uint2*)(sBhi + off) = hv;
        *(uint2*)(sBlo + off) = lv;
    }
    __syncthreads();

    const int wm = (w >> 1) * 16;
    const int wn = (w & 1) * 64;
    float acc[8][4];
#pragma unroll
    for (int i = 0; i < 8; i++)
#pragma unroll
        for (int j = 0; j < 4; j++) acc[i][j] = 0.f;

    const int arow = wm + (l & 15);
    const int acol = (l >> 4) << 3;
    const int browb = wn + ((l >> 4) & 1) * 8 + (l & 7);
    const int bcol  = ((l >> 3) & 1) << 3;

#pragma unroll
    for (int pass = 0; pass < 3; pass++) {
        const __nv_bfloat16* pA = (pass == 2) ? sAlo : sAhi;
        const __nv_bfloat16* pB = (pass == 1) ? sBlo : sBhi;
#pragma unroll
        for (int kc = 0; kc < 8; kc++) {
            const int k0 = kc * 16;
            uint32_t afr[4];
            ldsm_x4(afr, smem_u32(pA + arow * SMP + k0 + acol));
#pragma unroll
            for (int sn2 = 0; sn2 < 4; sn2++) {
                uint32_t bfr[4];
                ldsm_x4(bfr, smem_u32(pB + (browb + sn2 * 16) * SMP + k0 + bcol));
                mma_bf16(acc[sn2 * 2 + 0], afr, bfr + 0);
                mma_bf16(acc[sn2 * 2 + 1], afr, bfr + 2);
            }
        }
    }

    const int g = l >> 2, tq = l & 3;
    const int row0 = mBase + wm + g;
    const float m0 = (row0 < NN) ? 1.f : 0.f;
    const float m1 = (row0 + 8 < NN) ? 1.f : 0.f;
#pragma unroll
    for (int sn = 0; sn < 8; sn++) {
        int col = wn + sn * 8 + tq * 2;
        float* p0 = C + (size_t)row0 * DD + col;
        *(float2*)p0            = make_float2(acc[sn][0], acc[sn][1]);
        *(float2*)(p0 + 8 * DD) = make_float2(acc[sn][2], acc[sn][3]);
        float v0 = m0 * acc[sn][0], v1 = m0 * acc[sn][1];
        float v2 = m1 * acc[sn][2], v3 = m1 * acc[sn][3];
        float cs0 = v0 + v2, cs1 = v1 + v3;
        float cq0 = v0 * v0 + v2 * v2, cq1 = v1 * v1 + v3 * v3;
#pragma unroll
        for (int dlt = 16; dlt >= 4; dlt >>= 1) {
            cs0 += __shfl_down_sync(0xffffffffu, cs0, dlt);
            cs1 += __shfl_down_sync(0xffffffffu, cs1, dlt);
            cq0 += __shfl_down_sync(0xffffffffu, cq0, dlt);
            cq1 += __shfl_down_sync(0xffffffffu, cq1, dlt);
        }
        if (l < 4) {
            int c0 = wn + sn * 8 + l * 2;
            atomicAdd(&colS[c0], cs0);  atomicAdd(&colS[c0 + 1], cs1);
            atomicAdd(&colQ[c0], cq0);  atomicAdd(&colQ[c0 + 1], cq1);
        }
    }
    __syncthreads();
    if (t < DD) {
        atomicAdd(statS + t, colS[t]);
        atomicAdd(statQ + t, colQ[t]);
    }
}

// stats of relu(bn2(y2)); bn2 affine from raw stats at entry.
__global__ void __launch_bounds__(256) zstats_kernel(const float* __restrict__ y2,
                                                     const float* __restrict__ cs2,
                                                     const float* __restrict__ cq2,
                                                     const float* __restrict__ bn2g,
                                                     const float* __restrict__ bn2b,
                                                     float* __restrict__ cs,
                                                     float* __restrict__ cq)
{
    __shared__ float shS[8][DD];
    __shared__ float shQ[8][DD];
    __shared__ float sAf[DD], sCf[DD];
    const int t = threadIdx.x;
    const int c4 = (t & 31) * 4;
    const int rg = t >> 5;
    affine_from_stats(cs2, cq2, bn2g, bn2b, sAf, sCf, t);
    __syncthreads();
    float4 a = *(const float4*)(sAf + c4);
    float4 c = *(const float4*)(sCf + c4);
    float4 s = make_float4(0.f, 0.f, 0.f, 0.f), q = make_float4(0.f, 0.f, 0.f, 0.f);
    for (int m = blockIdx.x * 8 + rg; m < NN; m += gridDim.x * 8) {
        float4 v = *(const float4*)(y2 + (size_t)m * DD + c4);
        v.x = fmaxf(fmaf(v.x, a.x, c.x), 0.f);
        v.y = fmaxf(fmaf(v.y, a.y, c.y), 0.f);
        v.z = fmaxf(fmaf(v.z, a.z, c.z), 0.f);
        v.w = fmaxf(fmaf(v.w, a.w, c.w), 0.f);
        s.x += v.x; s.y += v.y; s.z += v.z; s.w += v.w;
        q.x += v.x * v.x; q.y += v.y * v.y; q.z += v.z * v.z; q.w += v.w * v.w;
    }
    *(float4*)&shS[rg][c4] = s;
    *(float4*)&shQ[rg][c4] = q;
    __syncthreads();
    if (t < DD) {
        float ts = 0.f, tqv = 0.f;
#pragma unroll
        for (int i = 0; i < 8; i++) { ts += shS[i][t]; tqv += shQ[i][t]; }
        atomicAdd(cs + t, ts);
        atomicAdd(cq + t, tqv);
    }
}

// out = bn3(relu(bn2(y2))) (+ optional relu). Affines from raw stats at entry.
__global__ void __launch_bounds__(256) apply_kernel(
    const float* __restrict__ y2,
    const float* __restrict__ cs2, const float* __restrict__ cq2,
    const float* __restrict__ bn2g, const float* __restrict__ bn2b,
    const float* __restrict__ cs3, const float* __restrict__ cq3,
    const float* __restrict__ bn3g, const float* __restrict__ bn3b,
    float* __restrict__ out, int doRelu)
{
    __shared__ float sA2[DD], sC2[DD], sA3[DD], sC3[DD];
    const int t = threadIdx.x;
    affine_from_stats(cs2, cq2, bn2g, bn2b, sA2, sC2, t);
    affine_from_stats(cs3, cq3, bn3g, bn3b, sA3, sC3, t);
    __syncthreads();
    int gid = blockIdx.x * blockDim.x + t;
    if (gid >= NN * (DD / 4)) return;
    int col4 = (gid & (DD / 4 - 1)) << 2;
    float4 v = ((const float4*)y2)[gid];
    float4 A2 = *(const float4*)(sA2 + col4);
    float4 C2 = *(const float4*)(sC2 + col4);
    float4 A3 = *(const float4*)(sA3 + col4);
    float4 C3 = *(const float4*)(sC3 + col4);
    v.x = fmaxf(fmaf(v.x, A2.x, C2.x), 0.f);
    v.y = fmaxf(fmaf(v.y, A2.y, C2.y), 0.f);
    v.z = fmaxf(fmaf(v.z, A2.z, C2.z), 0.f);
    v.w = fmaxf(fmaf(v.w, A2.w, C2.w), 0.f);
    v.x = fmaf(v.x, A3.x, C3.x);
    v.y = fmaf(v.y, A3.y, C3.y);
    v.z = fmaf(v.z, A3.z, C3.z);
    v.w = fmaf(v.w, A3.w, C3.w);
    if (doRelu) {
        v.x = fmaxf(v.x, 0.f); v.y = fmaxf(v.y, 0.f);
        v.z = fmaxf(v.z, 0.f); v.w = fmaxf(v.w, 0.f);
    }
    ((float4*)out)[gid] = v;
}

// ---------------- launch ----------------
extern "C" void kernel_launch(void* const* d_in, const int* in_sizes, int n_in,
                              void* d_out, int out_size)
{
    const float* h_in = (const float*)d_in[0];
    const int*   edges= (const int*)  d_in[1];
    const float* w    = (const float*)d_in[2];
    const float* W0s  = (const float*)d_in[3];
    const float* W1s  = (const float*)d_in[4];
    const float* bn1g = (const float*)d_in[5];
    const float* bn1b = (const float*)d_in[6];
    const float* bn2g = (const float*)d_in[7];
    const float* bn2b = (const float*)d_in[8];
    const float* bn3g = (const float*)d_in[9];
    const float* bn3b = (const float*)d_in[10];
    const int* src = edges;
    const int* dst = edges + EE;

    float *B1, *B2, *sS, *sQ;
    __nv_bfloat16 *bthi, *btlo;
    int *cnt, *startA, *cur, *bsum;
    int2 *ssw;
    cudaGetSymbolAddress((void**)&B1,   g_B1);
    cudaGetSymbolAddress((void**)&B2,   g_B2);
    cudaGetSymbolAddress((void**)&sS,   g_statS);
    cudaGetSymbolAddress((void**)&sQ,   g_statQ);
    cudaGetSymbolAddress((void**)&bthi, g_bthi);
    cudaGetSymbolAddress((void**)&btlo, g_btlo);
    cudaGetSymbolAddress((void**)&cnt,  g_countArr);
    cudaGetSymbolAddress((void**)&startA, g_startArr);
    cudaGetSymbolAddress((void**)&cur,  g_curArr);
    cudaGetSymbolAddress((void**)&bsum, g_bsum);
    cudaGetSymbolAddress((void**)&ssw,  g_ssw);

    const int GEMM_SMEM = (64 + 64 + 128 + 128) * SMP * 2;   // 104448 B
    cudaFuncSetAttribute(gemm_mma_kernel,
                         cudaFuncAttributeMaxDynamicSharedMemorySize, GEMM_SMEM);

    const int EGRID = (EE + 255) / 256;
    const int NGRID = (NN + 255) / 256;
    const int WGRID = (NN * 32 + 255) / 256;   // 6250 (warp per node)

    zero_kernel <<<NGRID, 256>>>(cnt, sS, sQ);
    hist_kernel <<<EGRID, 256>>>(dst, cnt);
    scan1_kernel<<<NBLK, 512>>>(cnt, startA, bsum);
    scan3_kernel<<<NGRID, 256>>>(startA, bsum, cur);
    fill_kernel <<<EGRID, 256>>>(src, dst, w, cur, ssw);
    wprep_all_kernel<<<(6 * DD * DD + 255) / 256, 256>>>(W0s, W1s, bthi, btlo);

    // Aliasing per layer:
    //   gather: reads h (B2, or h_in layer0) -> writes x (B1)
    //   gemm1 : reads B1 -> writes y (B2)     [h dead]
    //   gemm2 : reads B2 -> writes y2 (B1)    [x dead]
    //   zstats: reads B1
    //   apply : reads B1 -> writes h (B2)     [y dead]   (last layer -> d_out)
    for (int i = 0; i < LL; i++) {
        float *s1 = sS + (i * 3 + 0) * DD, *q1 = sQ + (i * 3 + 0) * DD;
        float *s2 = sS + (i * 3 + 1) * DD, *q2 = sQ + (i * 3 + 1) * DD;
        float *s3 = sS + (i * 3 + 2) * DD, *q3 = sQ + (i * 3 + 2) * DD;

        const float* hsrc = (i == 0) ? h_in : B2;
        gather_kernel<<<WGRID, 256>>>(hsrc, startA, cnt, ssw, B1);

        const __nv_bfloat16* b0h = bthi + (i * 2 + 0) * DD * DD;
        const __nv_bfloat16* b0l = btlo + (i * 2 + 0) * DD * DD;
        const __nv_bfloat16* b1h = bthi + (i * 2 + 1) * DD * DD;
        const __nv_bfloat16* b1l = btlo + (i * 2 + 1) * DD * DD;

        gemm_mma_kernel<<<GTILES, 256, GEMM_SMEM>>>(
            B1, b0h, b0l, B2, nullptr, nullptr, nullptr, nullptr, 0, s1, q1);
        gemm_mma_kernel<<<GTILES, 256, GEMM_SMEM>>>(
            B2, b1h, b1l, B1, s1, q1, bn1g + i * DD, bn1b + i * DD, 1, s2, q2);
        zstats_kernel<<<250, 256>>>(B1, s2, q2, bn2g + i * DD, bn2b + i * DD, s3, q3);

        int last = (i == LL - 1);
        apply_kernel<<<WGRID, 256>>>(B1, s2, q2, bn2g + i * DD, bn2b + i * DD,
                                     s3, q3, bn3g + i * DD, bn3b + i * DD,
                                     last ? (float*)d_out : B2, last ? 0 : 1);
    }
}